// round 6
// baseline (speedup 1.0000x reference)
#include <cuda_runtime.h>
#include <cuda_bf16.h>

// Problem constants
#define M_ROWS  200000      // BATCH * SIM_T
#define K_DIM   784
#define N1      100
#define T_STEPS 2000
#define BATCH   100
#define N2      10

// Scratch (z1 padded +4 rows, z2t padded +8 floats: unguarded prefetch)
__device__ float g_z1[(size_t)(M_ROWS + 4) * N1];           // 80 MB
__device__ float g_T1[(size_t)M_ROWS * N1];                 // 80 MB
__device__ float g_z2t[(size_t)BATCH * N2 * T_STEPS + 8];   // 8 MB
__device__ __nv_bfloat16 g_W1h[112 * K_DIM];
__device__ __nv_bfloat16 g_W1l[112 * K_DIM];

// ---------------------------------------------------------------------------
// helpers
// ---------------------------------------------------------------------------
__device__ __forceinline__ unsigned pack_bf16x2(float fhi, float flo) {
    unsigned r;
    asm("cvt.rn.bf16x2.f32 %0, %1, %2;" : "=r"(r) : "f"(fhi), "f"(flo));
    return r;
}
__device__ __forceinline__ void mma_bf16(float* c, const unsigned* a,
                                         unsigned b0, unsigned b1) {
    asm("mma.sync.aligned.m16n8k16.row.col.f32.bf16.bf16.f32 "
        "{%0,%1,%2,%3}, {%4,%5,%6,%7}, {%8,%9}, {%0,%1,%2,%3};"
        : "+f"(c[0]), "+f"(c[1]), "+f"(c[2]), "+f"(c[3])
        : "r"(a[0]), "r"(a[1]), "r"(a[2]), "r"(a[3]), "r"(b0), "r"(b1));
}

// ---------------------------------------------------------------------------
// K0: convert W1 -> bf16 hi/lo, padded to 112 rows
// ---------------------------------------------------------------------------
__global__ void w1_convert_kernel(const float* __restrict__ W1) {
    int idx = blockIdx.x * 256 + threadIdx.x;
    if (idx >= 112 * K_DIM) return;
    int r = idx / K_DIM;
    float w = (r < N1) ? W1[idx] : 0.f;
    __nv_bfloat16 hb = __float2bfloat16_rn(w);
    float hf = __bfloat162float(hb);
    g_W1h[idx] = hb;
    g_W1l[idx] = __float2bfloat16_rn(w - hf);
}

// ---------------------------------------------------------------------------
// K1: tensor-core GEMM  z1 = A @ W1^T  (bf16 3-split, fp32 acc) — unchanged
// ---------------------------------------------------------------------------
#define NSTAGE 49

__global__ void __launch_bounds__(256, 2)
gemm_z1_tc(const float* __restrict__ A) {
    __shared__ unsigned Ah[2][128 * 8];
    __shared__ unsigned Al[2][128 * 8];
    __shared__ unsigned Bh[2][112 * 8];
    __shared__ unsigned Bl[2][112 * 8];

    const int tid  = threadIdx.x;
    const int warp = tid >> 5, lane = tid & 31;
    const int g    = lane >> 2, tig = lane & 3;
    const int wm   = (warp >> 1) * 32;
    const int wn   = (warp & 1) * 56;
    const int row0 = blockIdx.x * 128;

    float acc[2][7][4];
#pragma unroll
    for (int i = 0; i < 2; i++)
#pragma unroll
        for (int j = 0; j < 7; j++)
#pragma unroll
            for (int q = 0; q < 4; q++) acc[i][j][q] = 0.f;

    float4 va[2];
    unsigned vbh[4], vbl[4];

    auto ldg_stage = [&](int s) {
        int k0 = s * 16;
#pragma unroll
        for (int i = 0; i < 2; i++) {
            int idx = tid + i * 256;
            int r = idx >> 2, q = idx & 3;
            int gr = row0 + r;
            va[i] = (gr < M_ROWS)
                  ? *(const float4*)(A + (size_t)gr * K_DIM + k0 + 4 * q)
                  : make_float4(0.f, 0.f, 0.f, 0.f);
        }
#pragma unroll
        for (int i = 0; i < 4; i++) {
            int idx = tid + i * 256;
            if (idx < 896) {
                int r = idx >> 3, j = idx & 7;
                size_t off = (size_t)r * (K_DIM / 2) + (k0 >> 1) + j;
                vbh[i] = ((const unsigned*)g_W1h)[off];
                vbl[i] = ((const unsigned*)g_W1l)[off];
            }
        }
    };
    auto sts_stage = [&](int buf) {
#pragma unroll
        for (int i = 0; i < 2; i++) {
            int idx = tid + i * 256;
            int r = idx >> 2, q = idx & 3;
            float4 v = va[i];
            unsigned h0 = pack_bf16x2(v.y, v.x);
            unsigned h1 = pack_bf16x2(v.w, v.z);
            float f0h = __uint_as_float(h0 << 16);
            float f1h = __uint_as_float(h0 & 0xffff0000u);
            float f2h = __uint_as_float(h1 << 16);
            float f3h = __uint_as_float(h1 & 0xffff0000u);
            unsigned l0 = pack_bf16x2(v.y - f1h, v.x - f0h);
            unsigned l1 = pack_bf16x2(v.w - f3h, v.z - f2h);
            int sw = r & 7;
            Ah[buf][r * 8 + ((2 * q)     ^ sw)] = h0;
            Ah[buf][r * 8 + ((2 * q + 1) ^ sw)] = h1;
            Al[buf][r * 8 + ((2 * q)     ^ sw)] = l0;
            Al[buf][r * 8 + ((2 * q + 1) ^ sw)] = l1;
        }
#pragma unroll
        for (int i = 0; i < 4; i++) {
            int idx = tid + i * 256;
            if (idx < 896) {
                int r = idx >> 3, j = idx & 7;
                Bh[buf][r * 8 + (j ^ (r & 7))] = vbh[i];
                Bl[buf][r * 8 + (j ^ (r & 7))] = vbl[i];
            }
        }
    };

    ldg_stage(0);
    sts_stage(0);
    __syncthreads();

#pragma unroll 1
    for (int s = 0; s < NSTAGE; s++) {
        if (s + 1 < NSTAGE) ldg_stage(s + 1);

        const int buf = s & 1;
        unsigned a_h[2][4], a_l[2][4];
#pragma unroll
        for (int mt = 0; mt < 2; mt++) {
            int r0 = wm + mt * 16 + g, r1 = r0 + 8;
            int s0 = r0 & 7, s1 = r1 & 7;
            a_h[mt][0] = Ah[buf][r0 * 8 + (tig ^ s0)];
            a_h[mt][1] = Ah[buf][r1 * 8 + (tig ^ s1)];
            a_h[mt][2] = Ah[buf][r0 * 8 + ((tig + 4) ^ s0)];
            a_h[mt][3] = Ah[buf][r1 * 8 + ((tig + 4) ^ s1)];
            a_l[mt][0] = Al[buf][r0 * 8 + (tig ^ s0)];
            a_l[mt][1] = Al[buf][r1 * 8 + (tig ^ s1)];
            a_l[mt][2] = Al[buf][r0 * 8 + ((tig + 4) ^ s0)];
            a_l[mt][3] = Al[buf][r1 * 8 + ((tig + 4) ^ s1)];
        }
#pragma unroll
        for (int nt = 0; nt < 7; nt++) {
            int n = wn + nt * 8 + g;
            int sn = n & 7;
            unsigned b0h = Bh[buf][n * 8 + (tig ^ sn)];
            unsigned b1h = Bh[buf][n * 8 + ((tig + 4) ^ sn)];
            unsigned b0l = Bl[buf][n * 8 + (tig ^ sn)];
            unsigned b1l = Bl[buf][n * 8 + ((tig + 4) ^ sn)];
#pragma unroll
            for (int mt = 0; mt < 2; mt++) {
                mma_bf16(acc[mt][nt], a_h[mt], b0h, b1h);
                mma_bf16(acc[mt][nt], a_h[mt], b0l, b1l);
                mma_bf16(acc[mt][nt], a_l[mt], b0h, b1h);
            }
        }

        if (s + 1 < NSTAGE) sts_stage((s + 1) & 1);
        __syncthreads();
    }

#pragma unroll
    for (int mt = 0; mt < 2; mt++) {
#pragma unroll
        for (int nt = 0; nt < 7; nt++) {
            int c = wn + nt * 8 + 2 * tig;
            if (c >= 99) continue;
            int r0g = row0 + wm + mt * 16 + g;
            if (r0g < M_ROWS) {
                float2 v = make_float2(acc[mt][nt][0], acc[mt][nt][1]);
                *(float2*)(g_z1 + (size_t)r0g * N1 + c) = v;
            }
            if (r0g + 8 < M_ROWS) {
                float2 v = make_float2(acc[mt][nt][2], acc[mt][nt][3]);
                *(float2*)(g_z1 + (size_t)(r0g + 8) * N1 + c) = v;
            }
        }
    }
}

// ---------------------------------------------------------------------------
// HH step math (identical to round 3/4)
// ---------------------------------------------------------------------------
__device__ __forceinline__ float ex2a(float x) {
    float r; asm("ex2.approx.f32 %0, %1;" : "=f"(r) : "f"(x)); return r;
}
__device__ __forceinline__ float rcpa(float x) {
    float r; asm("rcp.approx.f32 %0, %1;" : "=f"(r) : "f"(x)); return r;
}

#define L9   0.1602994489863f
#define L12  0.1202245867397f
#define L3   0.4808983469589f
#define BH_C 0.0023508962f
#define S0V  9.357622969e-14f

__device__ __forceinline__ void hh_step(float zk, float& V, float& m, float& n, float& h) {
    float mm   = m * m;
    float pow1 = 40.f * (mm * m) * h;
    float nn   = n * n;
    float pow2 = 35.f * (nn * nn);
    float Gs = 0.005f * (pow1 + pow2 + 0.3f);
    float E  = fmaf(pow1, 55.f, fmaf(pow2, -77.f, -19.5f));
    float num = fmaf(V, (1.f - Gs), 0.01f * (E + 1.5f + zk));
    float Vn = num * rcpa(1.f + Gs);

    float dM = Vn + 35.f;
    float uM = ex2a(dM * L9);
    float um1M = uM - 1.f;
    float sM = 0.005f * dM * fmaf(0.182f, uM, 0.124f);
    float mN = fmaf(0.00182f * dM, uM, (um1M - sM) * m) * rcpa(um1M + sM);

    float dN = Vn - 25.f;
    float uN = ex2a(dN * L9);
    float um1N = uN - 1.f;
    float sN = 0.005f * dN * fmaf(0.02f, uN, 0.002f);
    float nN = fmaf(0.0002f * dN, uN, (um1N - sN) * n) * rcpa(um1N + sN);

    float w  = ex2a((Vn + 90.f) * L12);
    float sH = fmaf(0.005f * BH_C, w * w, 0.00125f);
    float hN = fmaf(w - sH, h, 0.0025f) * rcpa(w + sH);

    if (Vn == 25.f)  nN = fmaf(0.99901f, n, 0.0018f) * (1.f / 1.00099f);
    if (Vn == -35.f) mN = fmaf(0.98623f, m, 0.01638f) * (1.f / 1.01377f);

    m = mN; n = nN; h = hN;
    V = Vn;
}

__device__ __forceinline__ float sigmoid_T(float V) {
    return rcpa(1.f + ex2a((20.f - V) * L3));
}

// ---------------------------------------------------------------------------
// K2: layer-1 scan, TWO chains per thread (c and c+50 of the same batch).
// Second chain's instructions fill the first chain's MUFU/FMA stall shadows.
// ---------------------------------------------------------------------------
__global__ void __launch_bounds__(128, 1)
hh_layer1_kernel() {
    const int u = blockIdx.x * 128 + threadIdx.x;
    if (u >= BATCH * 50) return;
    const int b = u / 50;
    const int j = u - b * 50;

    const float* zpA = g_z1 + (size_t)b * T_STEPS * N1 + j;
    const float* zpB = zpA + 50;
    float* tpA = g_T1 + (size_t)b * T_STEPS * N1 + j;
    float* tpB = tpA + 50;

    float VA = -70.f, mA = 0.f, nA = 0.f, hA = 1.f;
    float VB = -70.f, mB = 0.f, nB = 0.f, hB = 1.f;
    tpA[0] = S0V;
    tpB[0] = S0V;
    tpA += N1;  // points at store slot for s=0 (i.e., T1[s+1])
    tpB += N1;

    // depth-4 prefetch queues (z1 padded: unguarded loads)
    float pA0 = zpA[0],      pB0 = zpB[0];
    float pA1 = zpA[N1],     pB1 = zpB[N1];
    float pA2 = zpA[2 * N1], pB2 = zpB[2 * N1];
    float pA3 = zpA[3 * N1], pB3 = zpB[3 * N1];
    zpA += 4 * N1;  // next load target
    zpB += 4 * N1;

    for (int s4 = 0; s4 < T_STEPS; s4 += 4) {
#pragma unroll
        for (int jj = 0; jj < 4; jj++) {
            int s = s4 + jj;
            float zcA = pA0, zcB = pB0;
            pA0 = pA1; pA1 = pA2; pA2 = pA3; pA3 = *zpA; zpA += N1;
            pB0 = pB1; pB1 = pB2; pB2 = pB3; pB3 = *zpB; zpB += N1;
            hh_step(zcA, VA, mA, nA, hA);
            hh_step(zcB, VB, mB, nB, hB);
            if (s < T_STEPS - 1) {
                *tpA = sigmoid_T(VA);
                *tpB = sigmoid_T(VB);
            }
            tpA += N1; tpB += N1;
        }
    }
}

// ---------------------------------------------------------------------------
// K3: z2t[b*10+o][t] = sum_k T1[b][t][k] * W2[o][k]  (unchanged)
// ---------------------------------------------------------------------------
__global__ void __launch_bounds__(256, 4)
z2_kernel(const float* __restrict__ W2) {
    __shared__ float W2s[N1][12];

    const int tid = threadIdx.x;
    for (int i = tid; i < N1 * 12; i += 256) {
        int k = i / 12, o = i - k * 12;
        W2s[k][o] = (o < N2) ? W2[o * N1 + k] : 0.f;
    }
    __syncthreads();

    const int row = blockIdx.x * 256 + tid;
    if (row >= M_ROWS) return;
    const int b = row / T_STEPS;
    const int t = row - b * T_STEPS;

    const float4* tr = (const float4*)(g_T1 + (size_t)row * N1);
    float acc[12];
#pragma unroll
    for (int o = 0; o < 12; o++) acc[o] = 0.f;

#pragma unroll 5
    for (int k4 = 0; k4 < 25; k4++) {
        float4 tv = tr[k4];
        const float* tf = &tv.x;
#pragma unroll
        for (int kk = 0; kk < 4; kk++) {
            int k = k4 * 4 + kk;
            float4 w0 = *(const float4*)&W2s[k][0];
            float4 w1 = *(const float4*)&W2s[k][4];
            float4 w2 = *(const float4*)&W2s[k][8];
            float f = tf[kk];
            acc[0] = fmaf(f, w0.x, acc[0]);  acc[1] = fmaf(f, w0.y, acc[1]);
            acc[2] = fmaf(f, w0.z, acc[2]);  acc[3] = fmaf(f, w0.w, acc[3]);
            acc[4] = fmaf(f, w1.x, acc[4]);  acc[5] = fmaf(f, w1.y, acc[5]);
            acc[6] = fmaf(f, w1.z, acc[6]);  acc[7] = fmaf(f, w1.w, acc[7]);
            acc[8] = fmaf(f, w2.x, acc[8]);  acc[9] = fmaf(f, w2.y, acc[9]);
        }
    }
#pragma unroll
    for (int o = 0; o < N2; o++)
        g_z2t[((size_t)b * N2 + o) * T_STEPS + t] = acc[o];
}

// ---------------------------------------------------------------------------
// K4: layer-2 scan, TWO chains per thread (rows u and u+500 of z2t)
// ---------------------------------------------------------------------------
__global__ void __launch_bounds__(128, 1)
hh_layer2_kernel(float* __restrict__ out) {
    const int u = blockIdx.x * 128 + threadIdx.x;
    if (u >= 500) return;
    const int uA = u, uB = u + 500;
    const int bA = uA / N2, oA = uA - bA * N2;
    const int bB = uB / N2, oB = uB - bB * N2;

    const float4* zrowA = (const float4*)(g_z2t + (size_t)uA * T_STEPS);
    const float4* zrowB = (const float4*)(g_z2t + (size_t)uB * T_STEPS);
    float* opA = out + (size_t)bA * T_STEPS * N2 + oA;
    float* opB = out + (size_t)bB * T_STEPS * N2 + oB;

    float VA = -70.f, mA = 0.f, nA = 0.f, hA = 1.f;
    float VB = -70.f, mB = 0.f, nB = 0.f, hB = 1.f;
    opA[0] = S0V;
    opB[0] = S0V;
    opA += N2;
    opB += N2;

    float4 bufA0 = zrowA[0], bufA1 = zrowA[1];
    float4 bufB0 = zrowB[0], bufB1 = zrowB[1];

    for (int g = 0; g < T_STEPS / 4; g++) {
        float zvA[4] = {bufA0.x, bufA0.y, bufA0.z, bufA0.w};
        float zvB[4] = {bufB0.x, bufB0.y, bufB0.z, bufB0.w};
        bufA0 = bufA1; bufA1 = zrowA[g + 2];   // z2t padded: in-bounds
        bufB0 = bufB1; bufB1 = zrowB[g + 2];
#pragma unroll
        for (int jj = 0; jj < 4; jj++) {
            int s = g * 4 + jj;
            hh_step(zvA[jj], VA, mA, nA, hA);
            hh_step(zvB[jj], VB, mB, nB, hB);
            if (s < T_STEPS - 1) {
                *opA = sigmoid_T(VA);
                *opB = sigmoid_T(VB);
            }
            opA += N2; opB += N2;
        }
    }
}

// ---------------------------------------------------------------------------
extern "C" void kernel_launch(void* const* d_in, const int* in_sizes, int n_in,
                              void* d_out, int out_size) {
    const float* batch = (const float*)d_in[0];   // (100, 2000, 784)
    const float* W1    = (const float*)d_in[1];   // (100, 784)
    const float* W2    = (const float*)d_in[2];   // (10, 100)
    float* out = (float*)d_out;                   // (100, 2000, 10)

    w1_convert_kernel<<<(112 * K_DIM + 255) / 256, 256>>>(W1);
    gemm_z1_tc<<<(M_ROWS + 127) / 128, 256>>>(batch);
    hh_layer1_kernel<<<(BATCH * 50 + 127) / 128, 128>>>();
    z2_kernel<<<(M_ROWS + 255) / 256, 256>>>(W2);
    hh_layer2_kernel<<<(500 + 127) / 128, 128>>>(out);
}